// round 3
// baseline (speedup 1.0000x reference)
#include <cuda_runtime.h>
#include <cstdint>

#define BB 64
#define NN 1024

// Output layout (flattened reference tuple, all float32):
#define OFF_DONE 0
#define OFF_NM   1
#define OFF_ADJ  (1 + BB*NN)
#define OFF_FA   (OFF_ADJ + (size_t)BB*NN*NN)
#define OFF_PT   (OFF_FA + BB)
#define OFF_STEP (OFF_PT + BB)

__device__ float g_fp[BB * NN];     // fpresent[b, i]
__device__ float g_dlast[NN];       // dist[:, N-1] contiguous
__device__ float g_nmlast[BB];      // new_mask[b, N-1] (for `done` reduction)

__global__ void k_prep(const float* __restrict__ inputs,
                       const float* __restrict__ dist,
                       const float* __restrict__ mask,
                       const float* __restrict__ ptime,
                       const int*   __restrict__ pres,
                       const int*   __restrict__ fut,
                       float* out)
{
    int b = blockIdx.x;
    int j = threadIdx.x;

    int   pa = pres[b];
    float pt = ptime[b];

    float4 in4 = *reinterpret_cast<const float4*>(inputs + ((size_t)(b * NN + j)) * 4);
    float op = in4.x, cl = in4.y, dur = in4.z;
    float T0 = inputs[3];

    float dlast  = dist[(size_t)j * NN + (NN - 1)];
    float arrive = dist[(size_t)pa * NN + j] + pt;
    float wait   = fmaxf(0.0f, op - arrive);
    float t      = arrive + wait;

    bool c1 = t <= cl;
    bool c2 = ((t + dur) + dlast) <= T0;

    float m = mask[b * NN + j];
    if (j == pa) m = 0.0f;
    float nm = (c1 && c2) ? m : 0.0f;

    float fpres = t + dur;

    out[OFF_NM + b * NN + j] = nm;
    g_fp[b * NN + j] = fpres;
    if (b == 0) g_dlast[j] = dlast;
    if (j == NN - 1) g_nmlast[b] = nm;

    int fb = fut[b];
    if (j == fb) out[OFF_PT + b] = fpres;
    if (j == 0) {
        out[OFF_FA + b]   = (float)fb;
        out[OFF_STEP + b] = 1.0f;
    }
}

// adj kernel: RR dist rows staged SHIFTED in smem so that the 16B-aligned
// output float4 (j = 3+4t .. 6+4t; adj row base ≡ 1 mod 4 floats) can be fed
// by aligned LDS.128. Threads 0..254 own float4 slots; thread 255 handles the
// j ∈ {0,1,2,1023} scalars.
#define BT 16
#define RR 8
#define SROW 1040   // padded smem row stride (floats)

__global__ __launch_bounds__(256, 4) void k_adj(const float* __restrict__ inputs,
                                                const float* __restrict__ dist,
                                                float* out)
{
    extern __shared__ float sdist[];            // RR * SROW floats (~33 KB)

    const int ITILES = NN / RR;                 // 128
    int itile = blockIdx.x & (ITILES - 1);
    int b0    = (blockIdx.x / ITILES) * BT;
    int i0    = itile * RR;
    int tid   = threadIdx.x;

    if (blockIdx.x == 0 && tid == 0) {
        float any = 0.0f;
#pragma unroll
        for (int b = 0; b < BB; b++) any = fmaxf(any, g_nmlast[b]);
        out[OFF_DONE] = (any > 0.0f) ? 0.0f : 1.0f;
    }

    // Stage RR dist rows shifted by +1 float (vector gmem loads, scalar STS).
    {
        const float4* src = reinterpret_cast<const float4*>(dist + (size_t)i0 * NN);
#pragma unroll
        for (int k = 0; k < (RR * NN / 4) / 256; k++) {
            int idx = tid + 256 * k;            // float4 index in tile
            int r   = idx >> 8;                 // 256 float4 per row
            int c   = (idx & 255) * 4;
            float4 v = src[idx];
            float* d = sdist + r * SROW + 1 + c;
            d[0] = v.x; d[1] = v.y; d[2] = v.z; d[3] = v.w;
        }
    }

    const bool slot = (tid < 255);
    const int  jb   = 3 + 4 * tid;              // base j for slot threads

    // dlast does not depend on batch: hoist.
    float dl[4];
    if (slot) {
#pragma unroll
        for (int e = 0; e < 4; e++) dl[e] = g_dlast[jb + e];
    } else {
        dl[0] = g_dlast[0]; dl[1] = g_dlast[1];
        dl[2] = g_dlast[2]; dl[3] = g_dlast[NN - 1];
    }

    __syncthreads();

    const float* nm_base = out + OFF_NM;

    for (int bb = 0; bb < BT; bb++) {
        int b = b0 + bb;

        float op[4], cl[4], du[4], nm[4];
        if (slot) {
#pragma unroll
            for (int e = 0; e < 4; e++) {
                float4 in4 = *reinterpret_cast<const float4*>(
                    inputs + ((size_t)(b * NN + jb + e)) * 4);
                op[e] = in4.x; cl[e] = in4.y; du[e] = in4.z;
                nm[e] = nm_base[b * NN + jb + e];
            }
        } else {
            const int js[4] = {0, 1, 2, NN - 1};
#pragma unroll
            for (int e = 0; e < 4; e++) {
                float4 in4 = *reinterpret_cast<const float4*>(
                    inputs + ((size_t)(b * NN + js[e])) * 4);
                op[e] = in4.x; cl[e] = in4.y; du[e] = in4.z;
                nm[e] = nm_base[b * NN + js[e]];
            }
        }
        float Tb = inputs[((size_t)b * NN) * 4 + 3];

#pragma unroll
        for (int r = 0; r < RR; r++) {
            int   i  = i0 + r;
            float fp = g_fp[b * NN + i];
            float* orow = out + OFF_ADJ + ((size_t)(b * NN + i)) * NN;

            if (slot) {
                float4 dr = *reinterpret_cast<const float4*>(sdist + r * SROW + 1 + jb);
                float d4[4] = {dr.x, dr.y, dr.z, dr.w};
                float v[4];
#pragma unroll
                for (int e = 0; e < 4; e++) {
                    float arr2 = d4[e] + fp;
                    float w    = fmaxf(0.0f, op[e] - arr2);
                    float s    = arr2 + w;
                    bool a1 = s <= cl[e];
                    bool a2 = ((s + du[e]) + dl[e]) <= Tb;
                    float x = (a1 && a2) ? nm[e] : 0.0f;
                    if (jb + e == i) x = 1.0f;
                    v[e] = x;
                }
                __stcs(reinterpret_cast<float4*>(orow + jb),
                       make_float4(v[0], v[1], v[2], v[3]));
            } else {
                const int js[4] = {0, 1, 2, NN - 1};
#pragma unroll
                for (int e = 0; e < 4; e++) {
                    int j = js[e];
                    float arr2 = sdist[r * SROW + 1 + j] + fp;
                    float w    = fmaxf(0.0f, op[e] - arr2);
                    float s    = arr2 + w;
                    bool a1 = s <= cl[e];
                    bool a2 = ((s + du[e]) + dl[e]) <= Tb;
                    float x = (a1 && a2) ? nm[e] : 0.0f;
                    if (j == i) x = 1.0f;
                    __stcs(orow + j, x);
                }
            }
        }
    }
}

extern "C" void kernel_launch(void* const* d_in, const int* in_sizes, int n_in,
                              void* d_out, int out_size)
{
    const float* inputs = (const float*)d_in[0];   // (B, N, 4) f32
    const float* dist   = (const float*)d_in[1];   // (N, N)   f32
    const float* mask   = (const float*)d_in[2];   // (B, N)   f32
    const float* ptime  = (const float*)d_in[3];   // (B, 1)   f32
    const int*   pres   = (const int*)d_in[4];     // (B,)     i32
    const int*   fut    = (const int*)d_in[5];     // (B,)     i32
    float* out = (float*)d_out;

    const int SMEM = RR * SROW * sizeof(float);
    static bool attr_set = false;
    if (!attr_set) {
        cudaFuncSetAttribute(k_adj, cudaFuncAttributeMaxDynamicSharedMemorySize, SMEM);
        attr_set = true;
    }

    k_prep<<<BB, NN>>>(inputs, dist, mask, ptime, pres, fut, out);
    k_adj<<<(NN / RR) * (BB / BT), 256, SMEM>>>(inputs, dist, out);
}